// round 2
// baseline (speedup 1.0000x reference)
#include <cuda_runtime.h>
#include <math.h>

// Problem constants
#define BDIM   8
#define TDIM   2048
#define DDIM   1024
#define EDIM   4
#define KCB    64
#define NTAGS  512
#define G3D    3072   // 3*DDIM

// -------- scratch (device globals; no allocation allowed) --------
__device__ float g_X   [NTAGS * DDIM];        // gathered h rows per tag       (2 MB)
__device__ float g_Gih [NTAGS * G3D];         // W_ih @ x_t + b_ih             (6.3 MB)
__device__ float g_Ghh [(KCB + 1) * G3D];     // W_hh @ c_k + b_hh (row 64: zero state)
__device__ float g_cb  [(KCB + 1) * DDIM];    // codebook + zero row
__device__ float g_injT[KCB * DDIM];          // W_inj @ c_k
__device__ float g_cnorm[KCB];                // ||c_k||^2
__device__ float g_commit[BDIM];
__device__ int   g_nupd [BDIM];

// -------- gather h rows for each tag --------
__global__ void gather_x(const float* __restrict__ h,
                         const int* __restrict__ bidx,
                         const int* __restrict__ spos) {
    int t = blockIdx.x;
    int e = threadIdx.x;                       // 256 threads, float4 each
    const float4* src = (const float4*)(h + ((size_t)bidx[t] * TDIM + spos[t]) * DDIM);
    float4* dst = (float4*)(g_X + (size_t)t * DDIM);
    dst[e] = src[e];
}

// -------- codebook copy (+zero row) and norms --------
__global__ void prep_cb(const float* __restrict__ cb) {
    int k = blockIdx.x;            // 0..64
    int tid = threadIdx.x;         // 256
    float part = 0.f;
    for (int e = tid; e < DDIM; e += 256) {
        float v = (k < KCB) ? cb[(size_t)k * DDIM + e] : 0.f;
        g_cb[(size_t)k * DDIM + e] = v;
        part += v * v;
    }
    __shared__ float red[256];
    red[tid] = part;
    __syncthreads();
    for (int s = 128; s > 0; s >>= 1) {
        if (tid < s) red[tid] += red[tid + s];
        __syncthreads();
    }
    if (tid == 0 && k < KCB) g_cnorm[k] = red[0];
}

// -------- fp32 SIMT GEMM:  C[M,N] = A[M,K] * Bw[N,K]^T (+bias[n]) --------
// mode 0: A=g_X  C=g_Gih   mode 1: A=g_cb C=g_Ghh   mode 2: A=g_cb C=g_injT
__global__ __launch_bounds__(256)
void gemm_nt(int mode, const float* __restrict__ Bw, const float* __restrict__ bias,
             int M, int N, int K) {
    const float* A;
    float* C;
    if (mode == 0)      { A = g_X;  C = g_Gih;  }
    else if (mode == 1) { A = g_cb; C = g_Ghh;  }
    else                { A = g_cb; C = g_injT; }

    __shared__ __align__(16) float As[16][68];   // [k][m], padded row
    __shared__ __align__(16) float Bs[16][68];   // [k][n]

    const int bm = blockIdx.y * 64;
    const int bn = blockIdx.x * 64;
    const int tid = threadIdx.x;
    const int tx = tid & 15;       // 0..15 -> n
    const int ty = tid >> 4;       // 0..15 -> m
    const int lrow = tid >> 2;     // 0..63
    const int lk4  = (tid & 3) * 4;

    float acc[4][4] = {};

    for (int k0 = 0; k0 < K; k0 += 16) {
        int gm = bm + lrow;
        float4 av = (gm < M) ? *(const float4*)(A + (size_t)gm * K + k0 + lk4)
                             : make_float4(0.f, 0.f, 0.f, 0.f);
        As[lk4 + 0][lrow] = av.x; As[lk4 + 1][lrow] = av.y;
        As[lk4 + 2][lrow] = av.z; As[lk4 + 3][lrow] = av.w;

        int gn = bn + lrow;
        float4 bv = (gn < N) ? *(const float4*)(Bw + (size_t)gn * K + k0 + lk4)
                             : make_float4(0.f, 0.f, 0.f, 0.f);
        Bs[lk4 + 0][lrow] = bv.x; Bs[lk4 + 1][lrow] = bv.y;
        Bs[lk4 + 2][lrow] = bv.z; Bs[lk4 + 3][lrow] = bv.w;
        __syncthreads();

#pragma unroll
        for (int kk = 0; kk < 16; kk++) {
            float4 a = *(const float4*)&As[kk][ty * 4];
            float4 b = *(const float4*)&Bs[kk][tx * 4];
            acc[0][0] += a.x * b.x; acc[0][1] += a.x * b.y; acc[0][2] += a.x * b.z; acc[0][3] += a.x * b.w;
            acc[1][0] += a.y * b.x; acc[1][1] += a.y * b.y; acc[1][2] += a.y * b.z; acc[1][3] += a.y * b.w;
            acc[2][0] += a.z * b.x; acc[2][1] += a.z * b.y; acc[2][2] += a.z * b.z; acc[2][3] += a.z * b.w;
            acc[3][0] += a.w * b.x; acc[3][1] += a.w * b.y; acc[3][2] += a.w * b.z; acc[3][3] += a.w * b.w;
        }
        __syncthreads();
    }

#pragma unroll
    for (int i = 0; i < 4; i++) {
        int gm = bm + ty * 4 + i;
        if (gm >= M) continue;
#pragma unroll
        for (int j = 0; j < 4; j++) {
            int gn = bn + tx * 4 + j;
            if (gn < N)
                C[(size_t)gm * N + gn] = acc[i][j] + (bias ? bias[gn] : 0.f);
        }
    }
}

__device__ __forceinline__ float sigmoidf_(float x) { return 1.f / (1.f + expf(-x)); }

// -------- serial scan: one CTA per batch, 1024 threads --------
__global__ __launch_bounds__(1024)
void serial_scan(const int* __restrict__ bidx, const int* __restrict__ spos,
                 const int* __restrict__ tok, const int* __restrict__ ctag,
                 float* __restrict__ out) {
    const int b = blockIdx.x;
    const int tid = threadIdx.x;
    const int lane = tid & 31;
    const int w = tid >> 5;

    __shared__ __align__(16) float zbuf[DDIM];
    __shared__ float s_s[64];
    __shared__ float s_cn[64];
    __shared__ float s_zz;
    __shared__ int   s_idx;
    __shared__ int   s_code[4];
    __shared__ int   s_act;
    __shared__ int   sm_b[NTAGS];
    __shared__ int   sm_p[NTAGS];
    __shared__ int   sm_k[NTAGS];

    const int char_tag = ctag ? *ctag : 0;

    if (tid < NTAGS) { sm_b[tid] = bidx[tid]; sm_p[tid] = spos[tid]; sm_k[tid] = tok[tid]; }
    if (tid < 64) s_cn[tid] = g_cnorm[tid];
    if (tid == 0) {
        s_act = 0;
        s_code[0] = s_code[1] = s_code[2] = s_code[3] = KCB;  // zero state
    }
    __syncthreads();

    float commit_acc = 0.f;
    int nupd = 0;

    for (int t = 0; t < NTAGS; t++) {
        if (sm_b[t] != b) continue;
        const int act = s_act;
        const bool is_char = (sm_k[t] == char_tag);
        if (!is_char && act == 0) continue;  // complete no-op in the reference
        const int p = sm_p[t];
        const int slot_upd = (act + 3) & 3;  // (act-1) mod 4 (python semantics)
        const int cur_k = s_code[slot_upd];

        float zv;
        if (is_char) {
            zv = g_X[(size_t)t * DDIM + tid];
        } else {
            const float* gi = g_Gih + (size_t)t * G3D;
            const float* gh = g_Ghh + (size_t)cur_k * G3D;
            float rr = sigmoidf_(gi[tid]        + gh[tid]);
            float zg = sigmoidf_(gi[1024 + tid] + gh[1024 + tid]);
            float nn = tanhf(gi[2048 + tid] + rr * gh[2048 + tid]);
            float cur = g_cb[(size_t)cur_k * DDIM + tid];
            zv = (1.f - zg) * nn + zg * cur;
        }
        zbuf[tid] = zv;
        __syncthreads();

        // similarity pass: warp w -> codes 2w, 2w+1  (float4 over 1024 elems)
        {
            const int k0 = w * 2;
            const float4* c0 = (const float4*)(g_cb + (size_t)k0 * DDIM);
            const float4* c1 = (const float4*)(g_cb + (size_t)(k0 + 1) * DDIM);
            const float4* z4 = (const float4*)zbuf;
            float a0 = 0.f, a1 = 0.f;
#pragma unroll
            for (int j = 0; j < 8; j++) {
                float4 zz4 = z4[lane + 32 * j];
                float4 cv0 = c0[lane + 32 * j];
                float4 cv1 = c1[lane + 32 * j];
                a0 += zz4.x * cv0.x + zz4.y * cv0.y + zz4.z * cv0.z + zz4.w * cv0.w;
                a1 += zz4.x * cv1.x + zz4.y * cv1.y + zz4.z * cv1.z + zz4.w * cv1.w;
            }
#pragma unroll
            for (int off = 16; off; off >>= 1) {
                a0 += __shfl_down_sync(0xffffffffu, a0, off);
                a1 += __shfl_down_sync(0xffffffffu, a1, off);
            }
            if (lane == 0) { s_s[k0] = a0; s_s[k0 + 1] = a1; }
            if (w == 0) {   // ||z||^2 by warp 0
                float zq = 0.f;
#pragma unroll
                for (int j = 0; j < 8; j++) {
                    float4 zz4 = z4[lane + 32 * j];
                    zq += zz4.x * zz4.x + zz4.y * zz4.y + zz4.z * zz4.z + zz4.w * zz4.w;
                }
#pragma unroll
                for (int off = 16; off; off >>= 1) zq += __shfl_down_sync(0xffffffffu, zq, off);
                if (lane == 0) s_zz = zq;
            }
        }
        __syncthreads();

        // argmin + state update (warp 0)
        if (w == 0) {
            float d0 = s_cn[lane]      - 2.f * s_s[lane];
            float d1 = s_cn[lane + 32] - 2.f * s_s[lane + 32];
            int i0 = lane;
            if (d1 < d0) { d0 = d1; i0 = lane + 32; }
#pragma unroll
            for (int off = 16; off; off >>= 1) {
                float dn = __shfl_down_sync(0xffffffffu, d0, off);
                int   in_ = __shfl_down_sync(0xffffffffu, i0, off);
                if (dn < d0 || (dn == d0 && in_ < i0)) { d0 = dn; i0 = in_; }
            }
            if (lane == 0) {
                s_idx = i0;
                commit_acc += (s_zz + d0) * (1.f / 1024.f);  // mean||z-c||^2
                nupd++;
                int slot = is_char ? (act & 3) : slot_upd;
                s_code[slot] = i0;
                if (is_char) s_act = act + 1;
            }
        }
        __syncthreads();

        // injection write = precomputed table row (bit-identical given the index)
        const int qi = s_idx;
        out[((size_t)b * TDIM + p) * DDIM + tid] = g_injT[(size_t)qi * DDIM + tid];
    }

    if (tid == 0) { g_commit[b] = commit_acc; g_nupd[b] = nupd; }
}

__global__ void finalize_k(float* out, long long sidx, long long out_size) {
    if (threadIdx.x == 0 && blockIdx.x == 0) {
        float tc = 0.f;
        int nu = 0;
        for (int i = 0; i < BDIM; i++) { tc += g_commit[i]; nu += g_nupd[i]; }
        if (sidx < out_size)
            out[sidx] = tc / (float)(nu > 0 ? nu : 1);
    }
}

extern "C" void kernel_launch(void* const* d_in, const int* in_sizes, int n_in,
                              void* d_out, int out_size) {
    const float* h    = (const float*)d_in[0];
    const int*   bidx = (const int*)d_in[1];
    const int*   spos = (const int*)d_in[2];
    const int*   tok  = (const int*)d_in[3];
    const int*   ctag = nullptr;
    int o = 4;
    if (n_in >= 11) { ctag = (const int*)d_in[4]; o = 5; }
    const float* W_ih  = (const float*)d_in[o + 0];
    const float* W_hh  = (const float*)d_in[o + 1];
    const float* b_ih  = (const float*)d_in[o + 2];
    const float* b_hh  = (const float*)d_in[o + 3];
    const float* cb    = (const float*)d_in[o + 4];
    const float* W_inj = (const float*)d_in[o + 5];
    float* out = (float*)d_out;

    cudaMemsetAsync(out, 0, (size_t)out_size * sizeof(float), 0);
    gather_x<<<NTAGS, 256>>>(h, bidx, spos);
    prep_cb<<<KCB + 1, 256>>>(cb);
    // Gih = Xtags @ W_ih^T + b_ih     (512 x 3072, K=1024)
    gemm_nt<<<dim3(G3D / 64, NTAGS / 64), 256>>>(0, W_ih, b_ih, NTAGS, G3D, DDIM);
    // Ghh = [codebook;0] @ W_hh^T + b_hh   (65 x 3072)
    gemm_nt<<<dim3(G3D / 64, 2), 256>>>(1, W_hh, b_hh, KCB + 1, G3D, DDIM);
    // injT = codebook @ W_inj^T            (64 x 1024)
    gemm_nt<<<dim3(DDIM / 64, 1), 256>>>(2, W_inj, nullptr, KCB, DDIM, DDIM);
    serial_scan<<<BDIM, 1024>>>(bidx, spos, tok, ctag, out);
    finalize_k<<<1, 32>>>(out, (long long)BDIM * TDIM * DDIM, (long long)out_size);
}

// round 3
// speedup vs baseline: 1.2429x; 1.2429x over previous
#include <cuda_runtime.h>
#include <math.h>

// Problem constants
#define BDIM   8
#define TDIM   2048
#define DDIM   1024
#define EDIM   4
#define KCB    64
#define NTAGS  512
#define G3D    3072   // 3*DDIM

// -------- scratch (device globals; no allocation allowed) --------
__device__ float g_X   [NTAGS * DDIM];        // gathered h rows per tag
__device__ float g_Gih [NTAGS * G3D];         // W_ih @ x_t + b_ih
__device__ float g_Ghh [(KCB + 1) * G3D];     // W_hh @ c_k + b_hh (row 64: zero state)
__device__ float g_cb  [(KCB + 1) * DDIM];    // codebook + zero row
__device__ float g_injT[KCB * DDIM];          // W_inj @ c_k
__device__ float g_cnorm[KCB];                // ||c_k||^2
__device__ float g_commit[BDIM];
__device__ int   g_nupd [BDIM];

// ---- packed fp32x2 helpers (exact fp32 per lane) ----
#define FFMA2(acc, a, bsp) \
    asm("fma.rn.f32x2 %0, %1, %2, %0;" : "+l"(acc) : "l"(a), "l"(bsp))
#define SPLAT2(d, f) \
    asm("mov.b64 %0, {%1, %1};" : "=l"(d) : "r"(__float_as_uint(f)))

// -------- gather h rows for each tag (used by serial_scan char path) --------
__global__ void gather_x(const float* __restrict__ h,
                         const int* __restrict__ bidx,
                         const int* __restrict__ spos) {
    int t = blockIdx.x;
    int e = threadIdx.x;                       // 256 threads, float4 each
    const float4* src = (const float4*)(h + ((size_t)bidx[t] * TDIM + spos[t]) * DDIM);
    float4* dst = (float4*)(g_X + (size_t)t * DDIM);
    dst[e] = src[e];
}

// -------- codebook copy (+zero row) and norms --------
__global__ void prep_cb(const float* __restrict__ cb) {
    int k = blockIdx.x;            // 0..64
    int tid = threadIdx.x;         // 256
    float part = 0.f;
    for (int e = tid; e < DDIM; e += 256) {
        float v = (k < KCB) ? cb[(size_t)k * DDIM + e] : 0.f;
        g_cb[(size_t)k * DDIM + e] = v;
        part += v * v;
    }
    __shared__ float red[256];
    red[tid] = part;
    __syncthreads();
    for (int s = 128; s > 0; s >>= 1) {
        if (tid < s) red[tid] += red[tid + s];
        __syncthreads();
    }
    if (tid == 0 && k < KCB) g_cnorm[k] = red[0];
}

// ============================================================================
// Fused fp32 GEMM (f32x2 packed FMA, double-buffered), 3 problems in 1 grid:
//   blocks [0,384):   Gih  = gather(h)[512,1024] @ W_ih^T  + b_ih   (N=3072)
//   blocks [384,480): Ghh  = cb65 [65,1024]      @ W_hh^T  + b_hh   (N=3072)
//   blocks [480,496): injT = cb   [64,1024]      @ W_inj^T          (N=1024)
// Tile 64x64, BK=16, 128 threads, per-thread 8(m)x4(n) as 4 f32x2 m-pairs.
// ============================================================================
__global__ __launch_bounds__(128)
void fused_gemm(const float* __restrict__ h,
                const int* __restrict__ bidx, const int* __restrict__ spos,
                const float* __restrict__ W_ih, const float* __restrict__ b_ih,
                const float* __restrict__ W_hh, const float* __restrict__ b_hh,
                const float* __restrict__ W_inj)
{
    __shared__ __align__(16) float As[2][16][68];
    __shared__ __align__(16) float Bs[2][16][68];

    const int b = blockIdx.x;
    const float* Bw;
    const float* bias;
    float* C;
    const float* Abase = nullptr;
    int M, N, bm, bn, mode;
    if (b < 384) {
        mode = 0; M = NTAGS; N = G3D;
        bm = (b / 48) * 64; bn = (b % 48) * 64;
        Bw = W_ih; bias = b_ih; C = g_Gih;
    } else if (b < 480) {
        int t = b - 384;
        mode = 1; M = KCB + 1; N = G3D;
        bm = (t / 48) * 64; bn = (t % 48) * 64;
        Bw = W_hh; bias = b_hh; C = g_Ghh; Abase = g_cb;
    } else {
        int t = b - 480;
        mode = 2; M = KCB; N = DDIM;
        bm = 0; bn = t * 64;
        Bw = W_inj; bias = nullptr; C = g_injT; Abase = g_cb;
    }

    const int tid   = threadIdx.x;
    const int r     = tid >> 1;          // 0..63: tile row this thread loads
    const int halfq = (tid & 1) * 8;     // k-offset (floats) within BK=16

    // fixed row pointers (gather fused for mode 0)
    const float* aRow;
    {
        int gm = bm + r; if (gm > M - 1) gm = M - 1;
        if (mode == 0)
            aRow = h + ((size_t)bidx[gm] * TDIM + spos[gm]) * DDIM;
        else
            aRow = Abase + (size_t)gm * DDIM;
    }
    const float* bRow = Bw + (size_t)(bn + r) * DDIM;

    const int ty = tid >> 4;   // 0..7  -> m base = ty*8
    const int tx = tid & 15;   // 0..15 -> n base = tx*4

    unsigned long long acc[4][4];
#pragma unroll
    for (int p = 0; p < 4; p++)
#pragma unroll
        for (int j = 0; j < 4; j++) acc[p][j] = 0ull;

    // prologue: tile 0 -> buffer 0
    {
        float4 a0 = *(const float4*)(aRow + halfq);
        float4 a1 = *(const float4*)(aRow + halfq + 4);
        float4 v0 = *(const float4*)(bRow + halfq);
        float4 v1 = *(const float4*)(bRow + halfq + 4);
        As[0][halfq + 0][r] = a0.x; As[0][halfq + 1][r] = a0.y;
        As[0][halfq + 2][r] = a0.z; As[0][halfq + 3][r] = a0.w;
        As[0][halfq + 4][r] = a1.x; As[0][halfq + 5][r] = a1.y;
        As[0][halfq + 6][r] = a1.z; As[0][halfq + 7][r] = a1.w;
        Bs[0][halfq + 0][r] = v0.x; Bs[0][halfq + 1][r] = v0.y;
        Bs[0][halfq + 2][r] = v0.z; Bs[0][halfq + 3][r] = v0.w;
        Bs[0][halfq + 4][r] = v1.x; Bs[0][halfq + 5][r] = v1.y;
        Bs[0][halfq + 6][r] = v1.z; Bs[0][halfq + 7][r] = v1.w;
    }
    __syncthreads();

    int buf = 0;
#pragma unroll 1
    for (int k0 = 0; k0 < DDIM; k0 += 16) {
        float4 na0, na1, nb0, nb1;
        const bool more = (k0 + 16) < DDIM;
        if (more) {
            const float* ap = aRow + k0 + 16 + halfq;
            na0 = *(const float4*)(ap);
            na1 = *(const float4*)(ap + 4);
            const float* bp = bRow + k0 + 16 + halfq;
            nb0 = *(const float4*)(bp);
            nb1 = *(const float4*)(bp + 4);
        }

#pragma unroll
        for (int kk = 0; kk < 16; kk++) {
            ulonglong2 aA = *(const ulonglong2*)&As[buf][kk][ty * 8];
            ulonglong2 aB = *(const ulonglong2*)&As[buf][kk][ty * 8 + 4];
            float4 bv = *(const float4*)&Bs[buf][kk][tx * 4];
            unsigned long long s0, s1, s2, s3;
            SPLAT2(s0, bv.x); SPLAT2(s1, bv.y);
            SPLAT2(s2, bv.z); SPLAT2(s3, bv.w);
            FFMA2(acc[0][0], aA.x, s0); FFMA2(acc[0][1], aA.x, s1);
            FFMA2(acc[0][2], aA.x, s2); FFMA2(acc[0][3], aA.x, s3);
            FFMA2(acc[1][0], aA.y, s0); FFMA2(acc[1][1], aA.y, s1);
            FFMA2(acc[1][2], aA.y, s2); FFMA2(acc[1][3], aA.y, s3);
            FFMA2(acc[2][0], aB.x, s0); FFMA2(acc[2][1], aB.x, s1);
            FFMA2(acc[2][2], aB.x, s2); FFMA2(acc[2][3], aB.x, s3);
            FFMA2(acc[3][0], aB.y, s0); FFMA2(acc[3][1], aB.y, s1);
            FFMA2(acc[3][2], aB.y, s2); FFMA2(acc[3][3], aB.y, s3);
        }

        if (more) {
            int nb = buf ^ 1;
            As[nb][halfq + 0][r] = na0.x; As[nb][halfq + 1][r] = na0.y;
            As[nb][halfq + 2][r] = na0.z; As[nb][halfq + 3][r] = na0.w;
            As[nb][halfq + 4][r] = na1.x; As[nb][halfq + 5][r] = na1.y;
            As[nb][halfq + 6][r] = na1.z; As[nb][halfq + 7][r] = na1.w;
            Bs[nb][halfq + 0][r] = nb0.x; Bs[nb][halfq + 1][r] = nb0.y;
            Bs[nb][halfq + 2][r] = nb0.z; Bs[nb][halfq + 3][r] = nb0.w;
            Bs[nb][halfq + 4][r] = nb1.x; Bs[nb][halfq + 5][r] = nb1.y;
            Bs[nb][halfq + 6][r] = nb1.z; Bs[nb][halfq + 7][r] = nb1.w;
        }
        __syncthreads();
        buf ^= 1;
    }

    // epilogue
#pragma unroll
    for (int p = 0; p < 4; p++) {
        int gm0 = bm + ty * 8 + 2 * p;
#pragma unroll
        for (int j = 0; j < 4; j++) {
            int gn = bn + tx * 4 + j;
            float add = bias ? bias[gn] : 0.f;
            unsigned long long a = acc[p][j];
            float lo = __uint_as_float((unsigned)(a & 0xffffffffull)) + add;
            float hi = __uint_as_float((unsigned)(a >> 32)) + add;
            if (gm0 < M)     C[(size_t)gm0 * N + gn]       = lo;
            if (gm0 + 1 < M) C[(size_t)(gm0 + 1) * N + gn] = hi;
        }
    }
}

__device__ __forceinline__ float sigmoidf_(float x) { return 1.f / (1.f + expf(-x)); }

// -------- serial scan: one CTA per batch, 1024 threads (unchanged, verified) --------
__global__ __launch_bounds__(1024)
void serial_scan(const int* __restrict__ bidx, const int* __restrict__ spos,
                 const int* __restrict__ tok, const int* __restrict__ ctag,
                 float* __restrict__ out) {
    const int b = blockIdx.x;
    const int tid = threadIdx.x;
    const int lane = tid & 31;
    const int w = tid >> 5;

    __shared__ __align__(16) float zbuf[DDIM];
    __shared__ float s_s[64];
    __shared__ float s_cn[64];
    __shared__ float s_zz;
    __shared__ int   s_idx;
    __shared__ int   s_code[4];
    __shared__ int   s_act;
    __shared__ int   sm_b[NTAGS];
    __shared__ int   sm_p[NTAGS];
    __shared__ int   sm_k[NTAGS];

    const int char_tag = ctag ? *ctag : 0;

    if (tid < NTAGS) { sm_b[tid] = bidx[tid]; sm_p[tid] = spos[tid]; sm_k[tid] = tok[tid]; }
    if (tid < 64) s_cn[tid] = g_cnorm[tid];
    if (tid == 0) {
        s_act = 0;
        s_code[0] = s_code[1] = s_code[2] = s_code[3] = KCB;  // zero state
    }
    __syncthreads();

    float commit_acc = 0.f;
    int nupd = 0;

    for (int t = 0; t < NTAGS; t++) {
        if (sm_b[t] != b) continue;
        const int act = s_act;
        const bool is_char = (sm_k[t] == char_tag);
        if (!is_char && act == 0) continue;  // complete no-op in the reference
        const int p = sm_p[t];
        const int slot_upd = (act + 3) & 3;  // (act-1) mod 4 (python semantics)
        const int cur_k = s_code[slot_upd];

        float zv;
        if (is_char) {
            zv = g_X[(size_t)t * DDIM + tid];
        } else {
            const float* gi = g_Gih + (size_t)t * G3D;
            const float* gh = g_Ghh + (size_t)cur_k * G3D;
            float rr = sigmoidf_(gi[tid]        + gh[tid]);
            float zg = sigmoidf_(gi[1024 + tid] + gh[1024 + tid]);
            float nn = tanhf(gi[2048 + tid] + rr * gh[2048 + tid]);
            float cur = g_cb[(size_t)cur_k * DDIM + tid];
            zv = (1.f - zg) * nn + zg * cur;
        }
        zbuf[tid] = zv;
        __syncthreads();

        // similarity pass: warp w -> codes 2w, 2w+1  (float4 over 1024 elems)
        {
            const int k0 = w * 2;
            const float4* c0 = (const float4*)(g_cb + (size_t)k0 * DDIM);
            const float4* c1 = (const float4*)(g_cb + (size_t)(k0 + 1) * DDIM);
            const float4* z4 = (const float4*)zbuf;
            float a0 = 0.f, a1 = 0.f;
#pragma unroll
            for (int j = 0; j < 8; j++) {
                float4 zz4 = z4[lane + 32 * j];
                float4 cv0 = c0[lane + 32 * j];
                float4 cv1 = c1[lane + 32 * j];
                a0 += zz4.x * cv0.x + zz4.y * cv0.y + zz4.z * cv0.z + zz4.w * cv0.w;
                a1 += zz4.x * cv1.x + zz4.y * cv1.y + zz4.z * cv1.z + zz4.w * cv1.w;
            }
#pragma unroll
            for (int off = 16; off; off >>= 1) {
                a0 += __shfl_down_sync(0xffffffffu, a0, off);
                a1 += __shfl_down_sync(0xffffffffu, a1, off);
            }
            if (lane == 0) { s_s[k0] = a0; s_s[k0 + 1] = a1; }
            if (w == 0) {   // ||z||^2 by warp 0
                float zq = 0.f;
#pragma unroll
                for (int j = 0; j < 8; j++) {
                    float4 zz4 = z4[lane + 32 * j];
                    zq += zz4.x * zz4.x + zz4.y * zz4.y + zz4.z * zz4.z + zz4.w * zz4.w;
                }
#pragma unroll
                for (int off = 16; off; off >>= 1) zq += __shfl_down_sync(0xffffffffu, zq, off);
                if (lane == 0) s_zz = zq;
            }
        }
        __syncthreads();

        // argmin + state update (warp 0)
        if (w == 0) {
            float d0 = s_cn[lane]      - 2.f * s_s[lane];
            float d1 = s_cn[lane + 32] - 2.f * s_s[lane + 32];
            int i0 = lane;
            if (d1 < d0) { d0 = d1; i0 = lane + 32; }
#pragma unroll
            for (int off = 16; off; off >>= 1) {
                float dn = __shfl_down_sync(0xffffffffu, d0, off);
                int   in_ = __shfl_down_sync(0xffffffffu, i0, off);
                if (dn < d0 || (dn == d0 && in_ < i0)) { d0 = dn; i0 = in_; }
            }
            if (lane == 0) {
                s_idx = i0;
                commit_acc += (s_zz + d0) * (1.f / 1024.f);  // mean||z-c||^2
                nupd++;
                int slot = is_char ? (act & 3) : slot_upd;
                s_code[slot] = i0;
                if (is_char) s_act = act + 1;
            }
        }
        __syncthreads();

        // injection write = precomputed table row (bit-identical given the index)
        const int qi = s_idx;
        out[((size_t)b * TDIM + p) * DDIM + tid] = g_injT[(size_t)qi * DDIM + tid];
    }

    if (tid == 0) { g_commit[b] = commit_acc; g_nupd[b] = nupd; }
}

__global__ void finalize_k(float* out, long long sidx, long long out_size) {
    if (threadIdx.x == 0 && blockIdx.x == 0) {
        float tc = 0.f;
        int nu = 0;
        for (int i = 0; i < BDIM; i++) { tc += g_commit[i]; nu += g_nupd[i]; }
        if (sidx < out_size)
            out[sidx] = tc / (float)(nu > 0 ? nu : 1);
    }
}

extern "C" void kernel_launch(void* const* d_in, const int* in_sizes, int n_in,
                              void* d_out, int out_size) {
    const float* h    = (const float*)d_in[0];
    const int*   bidx = (const int*)d_in[1];
    const int*   spos = (const int*)d_in[2];
    const int*   tok  = (const int*)d_in[3];
    const int*   ctag = nullptr;
    int o = 4;
    if (n_in >= 11) { ctag = (const int*)d_in[4]; o = 5; }
    const float* W_ih  = (const float*)d_in[o + 0];
    const float* W_hh  = (const float*)d_in[o + 1];
    const float* b_ih  = (const float*)d_in[o + 2];
    const float* b_hh  = (const float*)d_in[o + 3];
    const float* cb    = (const float*)d_in[o + 4];
    const float* W_inj = (const float*)d_in[o + 5];
    float* out = (float*)d_out;

    cudaMemsetAsync(out, 0, (size_t)out_size * sizeof(float), 0);
    gather_x<<<NTAGS, 256>>>(h, bidx, spos);
    prep_cb<<<KCB + 1, 256>>>(cb);
    fused_gemm<<<496, 128>>>(h, bidx, spos, W_ih, b_ih, W_hh, b_hh, W_inj);
    serial_scan<<<BDIM, 1024>>>(bidx, spos, tok, ctag, out);
    finalize_k<<<1, 32>>>(out, (long long)BDIM * TDIM * DDIM, (long long)out_size);
}

// round 4
// speedup vs baseline: 1.3100x; 1.0540x over previous
#include <cuda_runtime.h>
#include <cuda_bf16.h>
#include <math.h>

// Problem constants
#define BDIM   8
#define TDIM   2048
#define DDIM   1024
#define EDIM   4
#define KCB    64
#define NTAGS  512
#define G3D    3072   // 3*DDIM

#define SCREEN_MARGIN 0.5f

// -------- scratch (device globals; no allocation allowed) --------
__device__ float g_X   [NTAGS * DDIM];        // gathered h rows per tag
__device__ float g_Gih [NTAGS * G3D];         // W_ih @ x_t + b_ih
__device__ float g_Ghh [(KCB + 1) * G3D];     // W_hh @ c_k + b_hh (row 64: zero state)
__device__ float g_cb  [(KCB + 1) * DDIM];    // codebook + zero row
__device__ float g_injT[KCB * DDIM];          // W_inj @ c_k
__device__ float g_cnorm[KCB];                // ||c_k||^2
__device__ float g_commit[BDIM];
__device__ int   g_nupd [BDIM];

// ---- packed fp32x2 helpers (exact fp32 per lane) ----
#define FFMA2(acc, a, bsp) \
    asm("fma.rn.f32x2 %0, %1, %2, %0;" : "+l"(acc) : "l"(a), "l"(bsp))
#define SPLAT2(d, f) \
    asm("mov.b64 %0, {%1, %1};" : "=l"(d) : "r"(__float_as_uint(f)))

// -------- gather h rows for each tag (used by serial_scan char path) --------
__global__ void gather_x(const float* __restrict__ h,
                         const int* __restrict__ bidx,
                         const int* __restrict__ spos) {
    int t = blockIdx.x;
    int e = threadIdx.x;                       // 256 threads, float4 each
    const float4* src = (const float4*)(h + ((size_t)bidx[t] * TDIM + spos[t]) * DDIM);
    float4* dst = (float4*)(g_X + (size_t)t * DDIM);
    dst[e] = src[e];
}

// -------- codebook copy (+zero row) and norms --------
__global__ void prep_cb(const float* __restrict__ cb) {
    int k = blockIdx.x;            // 0..64
    int tid = threadIdx.x;         // 256
    float part = 0.f;
    for (int e = tid; e < DDIM; e += 256) {
        float v = (k < KCB) ? cb[(size_t)k * DDIM + e] : 0.f;
        g_cb[(size_t)k * DDIM + e] = v;
        part += v * v;
    }
    __shared__ float red[256];
    red[tid] = part;
    __syncthreads();
    for (int s = 128; s > 0; s >>= 1) {
        if (tid < s) red[tid] += red[tid + s];
        __syncthreads();
    }
    if (tid == 0 && k < KCB) g_cnorm[k] = red[0];
}

// ============================================================================
// Fused fp32 GEMM (f32x2 packed FMA, double-buffered), 3 problems in 1 grid
// ============================================================================
__global__ __launch_bounds__(128)
void fused_gemm(const float* __restrict__ h,
                const int* __restrict__ bidx, const int* __restrict__ spos,
                const float* __restrict__ W_ih, const float* __restrict__ b_ih,
                const float* __restrict__ W_hh, const float* __restrict__ b_hh,
                const float* __restrict__ W_inj)
{
    __shared__ __align__(16) float As[2][16][68];
    __shared__ __align__(16) float Bs[2][16][68];

    const int b = blockIdx.x;
    const float* Bw;
    const float* bias;
    float* C;
    const float* Abase = nullptr;
    int M, N, bm, bn, mode;
    if (b < 384) {
        mode = 0; M = NTAGS; N = G3D;
        bm = (b / 48) * 64; bn = (b % 48) * 64;
        Bw = W_ih; bias = b_ih; C = g_Gih;
    } else if (b < 480) {
        int t = b - 384;
        mode = 1; M = KCB + 1; N = G3D;
        bm = (t / 48) * 64; bn = (t % 48) * 64;
        Bw = W_hh; bias = b_hh; C = g_Ghh; Abase = g_cb;
    } else {
        int t = b - 480;
        mode = 2; M = KCB; N = DDIM;
        bm = 0; bn = t * 64;
        Bw = W_inj; bias = nullptr; C = g_injT; Abase = g_cb;
    }

    const int tid   = threadIdx.x;
    const int r     = tid >> 1;
    const int halfq = (tid & 1) * 8;

    const float* aRow;
    {
        int gm = bm + r; if (gm > M - 1) gm = M - 1;
        if (mode == 0)
            aRow = h + ((size_t)bidx[gm] * TDIM + spos[gm]) * DDIM;
        else
            aRow = Abase + (size_t)gm * DDIM;
    }
    const float* bRow = Bw + (size_t)(bn + r) * DDIM;

    const int ty = tid >> 4;
    const int tx = tid & 15;

    unsigned long long acc[4][4];
#pragma unroll
    for (int p = 0; p < 4; p++)
#pragma unroll
        for (int j = 0; j < 4; j++) acc[p][j] = 0ull;

    {
        float4 a0 = *(const float4*)(aRow + halfq);
        float4 a1 = *(const float4*)(aRow + halfq + 4);
        float4 v0 = *(const float4*)(bRow + halfq);
        float4 v1 = *(const float4*)(bRow + halfq + 4);
        As[0][halfq + 0][r] = a0.x; As[0][halfq + 1][r] = a0.y;
        As[0][halfq + 2][r] = a0.z; As[0][halfq + 3][r] = a0.w;
        As[0][halfq + 4][r] = a1.x; As[0][halfq + 5][r] = a1.y;
        As[0][halfq + 6][r] = a1.z; As[0][halfq + 7][r] = a1.w;
        Bs[0][halfq + 0][r] = v0.x; Bs[0][halfq + 1][r] = v0.y;
        Bs[0][halfq + 2][r] = v0.z; Bs[0][halfq + 3][r] = v0.w;
        Bs[0][halfq + 4][r] = v1.x; Bs[0][halfq + 5][r] = v1.y;
        Bs[0][halfq + 6][r] = v1.z; Bs[0][halfq + 7][r] = v1.w;
    }
    __syncthreads();

    int buf = 0;
#pragma unroll 1
    for (int k0 = 0; k0 < DDIM; k0 += 16) {
        float4 na0, na1, nb0, nb1;
        const bool more = (k0 + 16) < DDIM;
        if (more) {
            const float* ap = aRow + k0 + 16 + halfq;
            na0 = *(const float4*)(ap);
            na1 = *(const float4*)(ap + 4);
            const float* bp = bRow + k0 + 16 + halfq;
            nb0 = *(const float4*)(bp);
            nb1 = *(const float4*)(bp + 4);
        }

#pragma unroll
        for (int kk = 0; kk < 16; kk++) {
            ulonglong2 aA = *(const ulonglong2*)&As[buf][kk][ty * 8];
            ulonglong2 aB = *(const ulonglong2*)&As[buf][kk][ty * 8 + 4];
            float4 bv = *(const float4*)&Bs[buf][kk][tx * 4];
            unsigned long long s0, s1, s2, s3;
            SPLAT2(s0, bv.x); SPLAT2(s1, bv.y);
            SPLAT2(s2, bv.z); SPLAT2(s3, bv.w);
            FFMA2(acc[0][0], aA.x, s0); FFMA2(acc[0][1], aA.x, s1);
            FFMA2(acc[0][2], aA.x, s2); FFMA2(acc[0][3], aA.x, s3);
            FFMA2(acc[1][0], aA.y, s0); FFMA2(acc[1][1], aA.y, s1);
            FFMA2(acc[1][2], aA.y, s2); FFMA2(acc[1][3], aA.y, s3);
            FFMA2(acc[2][0], aB.x, s0); FFMA2(acc[2][1], aB.x, s1);
            FFMA2(acc[2][2], aB.x, s2); FFMA2(acc[2][3], aB.x, s3);
            FFMA2(acc[3][0], aB.y, s0); FFMA2(acc[3][1], aB.y, s1);
            FFMA2(acc[3][2], aB.y, s2); FFMA2(acc[3][3], aB.y, s3);
        }

        if (more) {
            int nb = buf ^ 1;
            As[nb][halfq + 0][r] = na0.x; As[nb][halfq + 1][r] = na0.y;
            As[nb][halfq + 2][r] = na0.z; As[nb][halfq + 3][r] = na0.w;
            As[nb][halfq + 4][r] = na1.x; As[nb][halfq + 5][r] = na1.y;
            As[nb][halfq + 6][r] = na1.z; As[nb][halfq + 7][r] = na1.w;
            Bs[nb][halfq + 0][r] = nb0.x; Bs[nb][halfq + 1][r] = nb0.y;
            Bs[nb][halfq + 2][r] = nb0.z; Bs[nb][halfq + 3][r] = nb0.w;
            Bs[nb][halfq + 4][r] = nb1.x; Bs[nb][halfq + 5][r] = nb1.y;
            Bs[nb][halfq + 6][r] = nb1.z; Bs[nb][halfq + 7][r] = nb1.w;
        }
        __syncthreads();
        buf ^= 1;
    }

#pragma unroll
    for (int p = 0; p < 4; p++) {
        int gm0 = bm + ty * 8 + 2 * p;
#pragma unroll
        for (int j = 0; j < 4; j++) {
            int gn = bn + tx * 4 + j;
            float add = bias ? bias[gn] : 0.f;
            unsigned long long a = acc[p][j];
            float lo = __uint_as_float((unsigned)(a & 0xffffffffull)) + add;
            float hi = __uint_as_float((unsigned)(a >> 32)) + add;
            if (gm0 < M)     C[(size_t)gm0 * N + gn]       = lo;
            if (gm0 + 1 < M) C[(size_t)(gm0 + 1) * N + gn] = hi;
        }
    }
}

__device__ __forceinline__ float sigmoidf_(float x) { return 1.f / (1.f + expf(-x)); }

// ============================================================================
// serial scan: one CTA per batch, 1024 threads.
// bf16 smem-resident codebook screen + exact fp32 recheck of flagged codes.
// Dynamic smem: 64 x 512 __nv_bfloat162 codebook (128KB).
// ============================================================================
__global__ __launch_bounds__(1024)
void serial_scan(const int* __restrict__ bidx, const int* __restrict__ spos,
                 const int* __restrict__ tok, const int* __restrict__ ctag,
                 float* __restrict__ out) {
    extern __shared__ __align__(16) __nv_bfloat162 s_cbh[];   // [KCB][512]

    const int b = blockIdx.x;
    const int tid = threadIdx.x;
    const int lane = tid & 31;
    const int w = tid >> 5;

    __shared__ __align__(16) float zbuf[DDIM];
    __shared__ __align__(16) __nv_bfloat162 zbh[DDIM / 2];
    __shared__ float s_s[64];     // screened dots
    __shared__ float s_cn[64];
    __shared__ float s_d[64];     // exact rechecked distances (INF if not cand)
    __shared__ unsigned s_f0, s_f1;
    __shared__ int   s_idx;
    __shared__ int   s_code[4];
    __shared__ int   s_act;
    __shared__ int   sm_b[NTAGS];
    __shared__ int   sm_p[NTAGS];
    __shared__ int   sm_k[NTAGS];

    const int char_tag = ctag ? *ctag : 0;

    if (tid < NTAGS) { sm_b[tid] = bidx[tid]; sm_p[tid] = spos[tid]; sm_k[tid] = tok[tid]; }
    if (tid < 64) s_cn[tid] = g_cnorm[tid];
    if (tid == 0) {
        s_act = 0;
        s_code[0] = s_code[1] = s_code[2] = s_code[3] = KCB;  // zero state
    }
    // load bf16 codebook into smem (once)
    for (int idx = tid; idx < KCB * (DDIM / 2); idx += 1024) {
        int k = idx >> 9, e = idx & 511;
        float2 v = make_float2(g_cb[(size_t)k * DDIM + 2 * e],
                               g_cb[(size_t)k * DDIM + 2 * e + 1]);
        s_cbh[idx] = __floats2bfloat162_rn(v.x, v.y);
    }
    __syncthreads();

    float commit_acc = 0.f;
    int nupd = 0;

    for (int t = 0; t < NTAGS; t++) {
        if (sm_b[t] != b) continue;
        const int act = s_act;
        const bool is_char = (sm_k[t] == char_tag);
        if (!is_char && act == 0) continue;  // complete no-op in the reference
        const int p = sm_p[t];
        const int slot_upd = (act + 3) & 3;
        const int cur_k = s_code[slot_upd];

        // ---- phase A: compute z, write fp32 + bf16 copies ----
        float zv;
        if (is_char) {
            zv = g_X[(size_t)t * DDIM + tid];
        } else {
            const float* gi = g_Gih + (size_t)t * G3D;
            const float* gh = g_Ghh + (size_t)cur_k * G3D;
            float rr = sigmoidf_(gi[tid]        + gh[tid]);
            float zg = sigmoidf_(gi[1024 + tid] + gh[1024 + tid]);
            float nn = tanhf(gi[2048 + tid] + rr * gh[2048 + tid]);
            float cur = g_cb[(size_t)cur_k * DDIM + tid];
            zv = (1.f - zg) * nn + zg * cur;
        }
        zbuf[tid] = zv;
        {
            float partner = __shfl_xor_sync(0xffffffffu, zv, 1);
            if ((tid & 1) == 0)
                zbh[tid >> 1] = __floats2bfloat162_rn(zv, partner);
        }
        __syncthreads();

        // ---- phase B: bf16 screen, warp w -> codes 2w, 2w+1 ----
        {
            const int k0 = w * 2;
            const uint2* c0 = (const uint2*)(s_cbh + (size_t)k0 * 512);
            const uint2* c1 = (const uint2*)(s_cbh + (size_t)(k0 + 1) * 512);
            const uint2* zz = (const uint2*)zbh;
            float a0 = 0.f, a1 = 0.f;
#pragma unroll
            for (int j = 0; j < 8; j++) {
                uint2 zp = zz[lane + 32 * j];
                float2 zl = __bfloat1622float2(*(const __nv_bfloat162*)&zp.x);
                float2 zh = __bfloat1622float2(*(const __nv_bfloat162*)&zp.y);
                uint2 cp = c0[lane + 32 * j];
                float2 cl = __bfloat1622float2(*(const __nv_bfloat162*)&cp.x);
                float2 ch = __bfloat1622float2(*(const __nv_bfloat162*)&cp.y);
                a0 += zl.x * cl.x + zl.y * cl.y + zh.x * ch.x + zh.y * ch.y;
                cp = c1[lane + 32 * j];
                cl = __bfloat1622float2(*(const __nv_bfloat162*)&cp.x);
                ch = __bfloat1622float2(*(const __nv_bfloat162*)&cp.y);
                a1 += zl.x * cl.x + zl.y * cl.y + zh.x * ch.x + zh.y * ch.y;
            }
#pragma unroll
            for (int off = 16; off; off >>= 1) {
                a0 += __shfl_down_sync(0xffffffffu, a0, off);
                a1 += __shfl_down_sync(0xffffffffu, a1, off);
            }
            if (lane == 0) { s_s[k0] = a0; s_s[k0 + 1] = a1; }
        }
        __syncthreads();

        // ---- phase C: warp 0 flags candidates within margin of screened min ----
        if (w == 0) {
            float d0 = s_cn[lane]      - 2.f * s_s[lane];
            float d1 = s_cn[lane + 32] - 2.f * s_s[lane + 32];
            float mm = fminf(d0, d1);
#pragma unroll
            for (int off = 16; off; off >>= 1)
                mm = fminf(mm, __shfl_down_sync(0xffffffffu, mm, off));
            mm = __shfl_sync(0xffffffffu, mm, 0);
            unsigned f0 = __ballot_sync(0xffffffffu, d0 <= mm + SCREEN_MARGIN);
            unsigned f1 = __ballot_sync(0xffffffffu, d1 <= mm + SCREEN_MARGIN);
            if (lane == 0) { s_f0 = f0; s_f1 = f1; }
        }
        __syncthreads();

        // ---- phase D: exact fp32 recheck of flagged codes (warp w -> 2w,2w+1) ----
        {
            const unsigned f0 = s_f0, f1 = s_f1;
            const float4* z4 = (const float4*)zbuf;
#pragma unroll
            for (int jj = 0; jj < 2; jj++) {
                int j = 2 * w + jj;
                bool fl = ((j < 32 ? (f0 >> j) : (f1 >> (j - 32))) & 1u) != 0;
                float dx = INFINITY;
                if (fl) {
                    const float4* cr = (const float4*)(g_cb + (size_t)j * DDIM);
                    float acc = 0.f;
#pragma unroll
                    for (int i = 0; i < 8; i++) {
                        float4 c = cr[lane + 32 * i];
                        float4 z = z4[lane + 32 * i];
                        float e0 = z.x - c.x, e1 = z.y - c.y;
                        float e2 = z.z - c.z, e3 = z.w - c.w;
                        acc += e0 * e0 + e1 * e1 + e2 * e2 + e3 * e3;
                    }
#pragma unroll
                    for (int off = 16; off; off >>= 1)
                        acc += __shfl_down_sync(0xffffffffu, acc, off);
                    dx = acc;
                }
                if (lane == 0) s_d[j] = dx;
            }
        }
        __syncthreads();

        // ---- phase E: warp 0 exact argmin (tie -> lowest index), state update ----
        if (w == 0) {
            float d0 = s_d[lane];
            float d1 = s_d[lane + 32];
            int i0 = lane;
            if (d1 < d0) { d0 = d1; i0 = lane + 32; }
#pragma unroll
            for (int off = 16; off; off >>= 1) {
                float dn = __shfl_down_sync(0xffffffffu, d0, off);
                int   in_ = __shfl_down_sync(0xffffffffu, i0, off);
                if (dn < d0 || (dn == d0 && in_ < i0)) { d0 = dn; i0 = in_; }
            }
            if (lane == 0) {
                s_idx = i0;
                commit_acc += d0 * (1.f / 1024.f);   // exact mean||z-c*||^2
                nupd++;
                int slot = is_char ? (act & 3) : slot_upd;
                s_code[slot] = i0;
                if (is_char) s_act = act + 1;
            }
        }
        __syncthreads();

        // ---- injection write = precomputed table row ----
        const int qi = s_idx;
        out[((size_t)b * TDIM + p) * DDIM + tid] = g_injT[(size_t)qi * DDIM + tid];
    }

    if (tid == 0) { g_commit[b] = commit_acc; g_nupd[b] = nupd; }
}

__global__ void finalize_k(float* out, long long sidx, long long out_size) {
    if (threadIdx.x == 0 && blockIdx.x == 0) {
        float tc = 0.f;
        int nu = 0;
        for (int i = 0; i < BDIM; i++) { tc += g_commit[i]; nu += g_nupd[i]; }
        if (sidx < out_size)
            out[sidx] = tc / (float)(nu > 0 ? nu : 1);
    }
}

extern "C" void kernel_launch(void* const* d_in, const int* in_sizes, int n_in,
                              void* d_out, int out_size) {
    const float* h    = (const float*)d_in[0];
    const int*   bidx = (const int*)d_in[1];
    const int*   spos = (const int*)d_in[2];
    const int*   tok  = (const int*)d_in[3];
    const int*   ctag = nullptr;
    int o = 4;
    if (n_in >= 11) { ctag = (const int*)d_in[4]; o = 5; }
    const float* W_ih  = (const float*)d_in[o + 0];
    const float* W_hh  = (const float*)d_in[o + 1];
    const float* b_ih  = (const float*)d_in[o + 2];
    const float* b_hh  = (const float*)d_in[o + 3];
    const float* cb    = (const float*)d_in[o + 4];
    const float* W_inj = (const float*)d_in[o + 5];
    float* out = (float*)d_out;

    static int smem_set = 0;
    if (!smem_set) {
        cudaFuncSetAttribute(serial_scan,
                             cudaFuncAttributeMaxDynamicSharedMemorySize,
                             KCB * (DDIM / 2) * (int)sizeof(__nv_bfloat162));
        smem_set = 1;
    }

    cudaMemsetAsync(out, 0, (size_t)out_size * sizeof(float), 0);
    gather_x<<<NTAGS, 256>>>(h, bidx, spos);
    prep_cb<<<KCB + 1, 256>>>(cb);
    fused_gemm<<<496, 128>>>(h, bidx, spos, W_ih, b_ih, W_hh, b_hh, W_inj);
    serial_scan<<<BDIM, 1024, KCB * (DDIM / 2) * (int)sizeof(__nv_bfloat162)>>>(
        bidx, spos, tok, ctag, out);
    finalize_k<<<1, 32>>>(out, (long long)BDIM * TDIM * DDIM, (long long)out_size);
}

// round 5
// speedup vs baseline: 1.4763x; 1.1270x over previous
#include <cuda_runtime.h>
#include <cuda_bf16.h>
#include <math.h>

// Problem constants
#define BDIM   8
#define TDIM   2048
#define DDIM   1024
#define EDIM   4
#define KCB    64
#define NTAGS  512
#define G3D    3072   // 3*DDIM

#define SCREEN_MARGIN 0.5f

// -------- scratch (device globals; no allocation allowed) --------
__device__ float g_X   [NTAGS * DDIM];        // gathered h rows per tag
__device__ float g_Gih [NTAGS * G3D];         // W_ih @ x_t + b_ih
__device__ float g_Ghh [(KCB + 1) * G3D];     // W_hh @ c_k + b_hh (row 64: zero state)
__device__ float g_cb  [(KCB + 1) * DDIM];    // codebook + zero row
__device__ float g_injT[KCB * DDIM];          // W_inj @ c_k
__device__ float g_cnorm[KCB];                // ||c_k||^2
__device__ float g_commit[BDIM];
__device__ int   g_nupd [BDIM];

// ---- packed fp32x2 helpers (exact fp32 per lane) ----
#define FFMA2(acc, a, bsp) \
    asm("fma.rn.f32x2 %0, %1, %2, %0;" : "+l"(acc) : "l"(a), "l"(bsp))
#define SPLAT2(d, f) \
    asm("mov.b64 %0, {%1, %1};" : "=l"(d) : "r"(__float_as_uint(f)))

// -------- gather h rows for each tag --------
__global__ void gather_x(const float* __restrict__ h,
                         const int* __restrict__ bidx,
                         const int* __restrict__ spos) {
    int t = blockIdx.x;
    int e = threadIdx.x;                       // 256 threads, float4 each
    const float4* src = (const float4*)(h + ((size_t)bidx[t] * TDIM + spos[t]) * DDIM);
    float4* dst = (float4*)(g_X + (size_t)t * DDIM);
    dst[e] = src[e];
}

// -------- codebook copy (+zero row) and norms --------
__global__ void prep_cb(const float* __restrict__ cb) {
    int k = blockIdx.x;            // 0..64
    int tid = threadIdx.x;         // 256
    float part = 0.f;
    for (int e = tid; e < DDIM; e += 256) {
        float v = (k < KCB) ? cb[(size_t)k * DDIM + e] : 0.f;
        g_cb[(size_t)k * DDIM + e] = v;
        part += v * v;
    }
    __shared__ float red[256];
    red[tid] = part;
    __syncthreads();
    for (int s = 128; s > 0; s >>= 1) {
        if (tid < s) red[tid] += red[tid + s];
        __syncthreads();
    }
    if (tid == 0 && k < KCB) g_cnorm[k] = red[0];
}

// ============================================================================
// Fused fp32 GEMM (f32x2 packed FMA, double-buffered), 3 problems in 1 grid
// ============================================================================
__global__ __launch_bounds__(128)
void fused_gemm(const float* __restrict__ h,
                const int* __restrict__ bidx, const int* __restrict__ spos,
                const float* __restrict__ W_ih, const float* __restrict__ b_ih,
                const float* __restrict__ W_hh, const float* __restrict__ b_hh,
                const float* __restrict__ W_inj)
{
    __shared__ __align__(16) float As[2][16][68];
    __shared__ __align__(16) float Bs[2][16][68];

    const int b = blockIdx.x;
    const float* Bw;
    const float* bias;
    float* C;
    const float* Abase = nullptr;
    int M, N, bm, bn, mode;
    if (b < 384) {
        mode = 0; M = NTAGS; N = G3D;
        bm = (b / 48) * 64; bn = (b % 48) * 64;
        Bw = W_ih; bias = b_ih; C = g_Gih;
    } else if (b < 480) {
        int t = b - 384;
        mode = 1; M = KCB + 1; N = G3D;
        bm = (t / 48) * 64; bn = (t % 48) * 64;
        Bw = W_hh; bias = b_hh; C = g_Ghh; Abase = g_cb;
    } else {
        int t = b - 480;
        mode = 2; M = KCB; N = DDIM;
        bm = 0; bn = t * 64;
        Bw = W_inj; bias = nullptr; C = g_injT; Abase = g_cb;
    }

    const int tid   = threadIdx.x;
    const int r     = tid >> 1;
    const int halfq = (tid & 1) * 8;

    const float* aRow;
    {
        int gm = bm + r; if (gm > M - 1) gm = M - 1;
        if (mode == 0)
            aRow = h + ((size_t)bidx[gm] * TDIM + spos[gm]) * DDIM;
        else
            aRow = Abase + (size_t)gm * DDIM;
    }
    const float* bRow = Bw + (size_t)(bn + r) * DDIM;

    const int ty = tid >> 4;
    const int tx = tid & 15;

    unsigned long long acc[4][4];
#pragma unroll
    for (int p = 0; p < 4; p++)
#pragma unroll
        for (int j = 0; j < 4; j++) acc[p][j] = 0ull;

    {
        float4 a0 = *(const float4*)(aRow + halfq);
        float4 a1 = *(const float4*)(aRow + halfq + 4);
        float4 v0 = *(const float4*)(bRow + halfq);
        float4 v1 = *(const float4*)(bRow + halfq + 4);
        As[0][halfq + 0][r] = a0.x; As[0][halfq + 1][r] = a0.y;
        As[0][halfq + 2][r] = a0.z; As[0][halfq + 3][r] = a0.w;
        As[0][halfq + 4][r] = a1.x; As[0][halfq + 5][r] = a1.y;
        As[0][halfq + 6][r] = a1.z; As[0][halfq + 7][r] = a1.w;
        Bs[0][halfq + 0][r] = v0.x; Bs[0][halfq + 1][r] = v0.y;
        Bs[0][halfq + 2][r] = v0.z; Bs[0][halfq + 3][r] = v0.w;
        Bs[0][halfq + 4][r] = v1.x; Bs[0][halfq + 5][r] = v1.y;
        Bs[0][halfq + 6][r] = v1.z; Bs[0][halfq + 7][r] = v1.w;
    }
    __syncthreads();

    int buf = 0;
#pragma unroll 1
    for (int k0 = 0; k0 < DDIM; k0 += 16) {
        float4 na0, na1, nb0, nb1;
        const bool more = (k0 + 16) < DDIM;
        if (more) {
            const float* ap = aRow + k0 + 16 + halfq;
            na0 = *(const float4*)(ap);
            na1 = *(const float4*)(ap + 4);
            const float* bp = bRow + k0 + 16 + halfq;
            nb0 = *(const float4*)(bp);
            nb1 = *(const float4*)(bp + 4);
        }

#pragma unroll
        for (int kk = 0; kk < 16; kk++) {
            ulonglong2 aA = *(const ulonglong2*)&As[buf][kk][ty * 8];
            ulonglong2 aB = *(const ulonglong2*)&As[buf][kk][ty * 8 + 4];
            float4 bv = *(const float4*)&Bs[buf][kk][tx * 4];
            unsigned long long s0, s1, s2, s3;
            SPLAT2(s0, bv.x); SPLAT2(s1, bv.y);
            SPLAT2(s2, bv.z); SPLAT2(s3, bv.w);
            FFMA2(acc[0][0], aA.x, s0); FFMA2(acc[0][1], aA.x, s1);
            FFMA2(acc[0][2], aA.x, s2); FFMA2(acc[0][3], aA.x, s3);
            FFMA2(acc[1][0], aA.y, s0); FFMA2(acc[1][1], aA.y, s1);
            FFMA2(acc[1][2], aA.y, s2); FFMA2(acc[1][3], aA.y, s3);
            FFMA2(acc[2][0], aB.x, s0); FFMA2(acc[2][1], aB.x, s1);
            FFMA2(acc[2][2], aB.x, s2); FFMA2(acc[2][3], aB.x, s3);
            FFMA2(acc[3][0], aB.y, s0); FFMA2(acc[3][1], aB.y, s1);
            FFMA2(acc[3][2], aB.y, s2); FFMA2(acc[3][3], aB.y, s3);
        }

        if (more) {
            int nb = buf ^ 1;
            As[nb][halfq + 0][r] = na0.x; As[nb][halfq + 1][r] = na0.y;
            As[nb][halfq + 2][r] = na0.z; As[nb][halfq + 3][r] = na0.w;
            As[nb][halfq + 4][r] = na1.x; As[nb][halfq + 5][r] = na1.y;
            As[nb][halfq + 6][r] = na1.z; As[nb][halfq + 7][r] = na1.w;
            Bs[nb][halfq + 0][r] = nb0.x; Bs[nb][halfq + 1][r] = nb0.y;
            Bs[nb][halfq + 2][r] = nb0.z; Bs[nb][halfq + 3][r] = nb0.w;
            Bs[nb][halfq + 4][r] = nb1.x; Bs[nb][halfq + 5][r] = nb1.y;
            Bs[nb][halfq + 6][r] = nb1.z; Bs[nb][halfq + 7][r] = nb1.w;
        }
        __syncthreads();
        buf ^= 1;
    }

#pragma unroll
    for (int p = 0; p < 4; p++) {
        int gm0 = bm + ty * 8 + 2 * p;
#pragma unroll
        for (int j = 0; j < 4; j++) {
            int gn = bn + tx * 4 + j;
            float add = bias ? bias[gn] : 0.f;
            unsigned long long a = acc[p][j];
            float lo = __uint_as_float((unsigned)(a & 0xffffffffull)) + add;
            float hi = __uint_as_float((unsigned)(a >> 32)) + add;
            if (gm0 < M)     C[(size_t)gm0 * N + gn]       = lo;
            if (gm0 + 1 < M) C[(size_t)(gm0 + 1) * N + gn] = hi;
        }
    }
}

__device__ __forceinline__ float sigmoidf_(float x) { return 1.f / (1.f + expf(-x)); }

// ============================================================================
// serial scan v3: precomputed schedule + register prefetch + speculative
// state prefetch + deferred injection writes. 4 barriers per step.
// Dynamic smem: bf16 codebook [KCB][512] (128KB).
// ============================================================================
__global__ __launch_bounds__(1024)
void serial_scan(const int* __restrict__ bidx, const int* __restrict__ spos,
                 const int* __restrict__ tok, const int* __restrict__ ctag,
                 float* __restrict__ out) {
    extern __shared__ __align__(16) __nv_bfloat162 s_cbh[];   // [KCB][512]

    const int b = blockIdx.x;
    const int tid = threadIdx.x;
    const int lane = tid & 31;
    const int w = tid >> 5;

    __shared__ __align__(16) float zbuf[DDIM];
    __shared__ __align__(16) __nv_bfloat162 zbh[DDIM / 2];
    __shared__ float s_s[64];     // screened dots
    __shared__ float s_cn[64];
    __shared__ float s_d[64];     // exact rechecked distances (INF if not cand)
    __shared__ int   s_idx;
    __shared__ int   s_code[4];
    __shared__ int   sm_b[NTAGS];
    __shared__ int   sm_p[NTAGS];
    __shared__ int   sm_k[NTAGS];
    // schedule
    __shared__ int   s_scan[NTAGS];
    __shared__ short s_t [NTAGS];
    __shared__ short s_p2[NTAGS];
    __shared__ unsigned char s_fl[NTAGS];   // bit0 is_char, bits[1:3) slot_w, bits[3:5) slot_r
    __shared__ unsigned char s_outk[NTAGS]; // chosen code per active step
    __shared__ int   s_nact;

    const int char_tag = ctag ? *ctag : 0;

    if (tid < NTAGS) { sm_b[tid] = bidx[tid]; sm_p[tid] = spos[tid]; sm_k[tid] = tok[tid]; }
    if (tid < 64) s_cn[tid] = g_cnorm[tid];
    if (tid == 0) {
        s_code[0] = s_code[1] = s_code[2] = s_code[3] = KCB;  // zero state
    }
    // load bf16 codebook into smem (once)
    for (int idx = tid; idx < KCB * (DDIM / 2); idx += 1024) {
        int k = idx >> 9, e = idx & 511;
        s_cbh[idx] = __floats2bfloat162_rn(g_cb[(size_t)k * DDIM + 2 * e],
                                           g_cb[(size_t)k * DDIM + 2 * e + 1]);
    }
    __syncthreads();

    // ---- build active-step schedule (token-id dependent only) ----
    int inb = 0, isch = 0;
    if (tid < NTAGS) {
        inb  = (sm_b[tid] == b) ? 1 : 0;
        isch = (inb && sm_k[tid] == char_tag) ? 1 : 0;
        s_scan[tid] = isch;
    }
    __syncthreads();
    // inclusive prefix over chars
    for (int off = 1; off < NTAGS; off <<= 1) {
        int v = 0;
        if (tid < NTAGS) { v = s_scan[tid]; if (tid >= off) v += s_scan[tid - off]; }
        __syncthreads();
        if (tid < NTAGS) s_scan[tid] = v;
        __syncthreads();
    }
    int chars_before = 0, active = 0;
    if (tid < NTAGS) {
        chars_before = s_scan[tid] - isch;
        active = (inb && (isch || chars_before > 0)) ? 1 : 0;
    }
    __syncthreads();
    if (tid < NTAGS) s_scan[tid] = active;
    __syncthreads();
    for (int off = 1; off < NTAGS; off <<= 1) {
        int v = 0;
        if (tid < NTAGS) { v = s_scan[tid]; if (tid >= off) v += s_scan[tid - off]; }
        __syncthreads();
        if (tid < NTAGS) s_scan[tid] = v;
        __syncthreads();
    }
    if (tid < NTAGS && active) {
        int pos = s_scan[tid] - 1;           // compacted index (order preserved)
        s_t [pos] = (short)tid;
        s_p2[pos] = (short)sm_p[tid];
        int act = chars_before;
        int sw = isch ? (act & 3) : ((act - 1) & 3);
        int sr = (act - 1) & 3;              // valid when needed (non-char => act>0)
        s_fl[pos] = (unsigned char)(isch | (sw << 1) | (sr << 3));
    }
    if (tid == NTAGS - 1) s_nact = s_scan[NTAGS - 1];
    __syncthreads();

    const int n_act = s_nact;
    float commit_acc = 0.f;

    // ---- prologue prefetch for step 0 ----
    int spec_k = -1;
    float pf_gi0 = 0.f, pf_gi1 = 0.f, pf_gi2 = 0.f, pf_x = 0.f;
    float pf_gh0 = 0.f, pf_gh1 = 0.f, pf_gh2 = 0.f, pf_cur = 0.f;
    if (n_act > 0) {
        int t0 = s_t[0];
        if (s_fl[0] & 1) {
            pf_x = g_X[(size_t)t0 * DDIM + tid];
        } else {
            const float* gi = g_Gih + (size_t)t0 * G3D;
            pf_gi0 = gi[tid]; pf_gi1 = gi[1024 + tid]; pf_gi2 = gi[2048 + tid];
        }
    }

    for (int i = 0; i < n_act; i++) {
        const unsigned fl = s_fl[i];
        const bool is_char = (fl & 1) != 0;
        const int  sw = (fl >> 1) & 3;
        const int  sr = (fl >> 3) & 3;
        const int  cur_k = is_char ? 0 : s_code[sr];

        // ---- phase A: z (prefetched inputs), bf16 copy, prefetch next Gih/X ----
        float zv;
        if (is_char) {
            zv = pf_x;
        } else {
            float gh0, gh1, gh2, cur;
            if (cur_k == spec_k) {
                gh0 = pf_gh0; gh1 = pf_gh1; gh2 = pf_gh2; cur = pf_cur;
            } else {
                const float* gh = g_Ghh + (size_t)cur_k * G3D;
                gh0 = gh[tid]; gh1 = gh[1024 + tid]; gh2 = gh[2048 + tid];
                cur = g_cb[(size_t)cur_k * DDIM + tid];
            }
            float rr = sigmoidf_(pf_gi0 + gh0);
            float zg = sigmoidf_(pf_gi1 + gh1);
            float nn = tanhf(pf_gi2 + rr * gh2);
            zv = (1.f - zg) * nn + zg * cur;
        }
        zbuf[tid] = zv;
        {
            float partner = __shfl_xor_sync(0xffffffffu, zv, 1);
            if ((tid & 1) == 0)
                zbh[tid >> 1] = __floats2bfloat162_rn(zv, partner);
        }
        if (i + 1 < n_act) {
            int t2 = s_t[i + 1];
            if (s_fl[i + 1] & 1) {
                pf_x = g_X[(size_t)t2 * DDIM + tid];
            } else {
                const float* gi = g_Gih + (size_t)t2 * G3D;
                pf_gi0 = gi[tid]; pf_gi1 = gi[1024 + tid]; pf_gi2 = gi[2048 + tid];
            }
        }
        __syncthreads();                       // sync 1

        // ---- phase B: bf16 screen, warp w -> codes 2w, 2w+1 ----
        {
            const int k0 = w * 2;
            const uint2* c0 = (const uint2*)(s_cbh + (size_t)k0 * 512);
            const uint2* c1 = (const uint2*)(s_cbh + (size_t)(k0 + 1) * 512);
            const uint2* zz = (const uint2*)zbh;
            float a0 = 0.f, a1 = 0.f;
#pragma unroll
            for (int j = 0; j < 8; j++) {
                uint2 zp = zz[lane + 32 * j];
                float2 zl = __bfloat1622float2(*(const __nv_bfloat162*)&zp.x);
                float2 zh = __bfloat1622float2(*(const __nv_bfloat162*)&zp.y);
                uint2 cp = c0[lane + 32 * j];
                float2 cl = __bfloat1622float2(*(const __nv_bfloat162*)&cp.x);
                float2 ch = __bfloat1622float2(*(const __nv_bfloat162*)&cp.y);
                a0 += zl.x * cl.x + zl.y * cl.y + zh.x * ch.x + zh.y * ch.y;
                cp = c1[lane + 32 * j];
                cl = __bfloat1622float2(*(const __nv_bfloat162*)&cp.x);
                ch = __bfloat1622float2(*(const __nv_bfloat162*)&cp.y);
                a1 += zl.x * cl.x + zl.y * cl.y + zh.x * ch.x + zh.y * ch.y;
            }
#pragma unroll
            for (int off = 16; off; off >>= 1) {
                a0 += __shfl_down_sync(0xffffffffu, a0, off);
                a1 += __shfl_down_sync(0xffffffffu, a1, off);
            }
            if (lane == 0) { s_s[k0] = a0; s_s[k0 + 1] = a1; }
        }
        __syncthreads();                       // sync 2

        // ---- phase C (all warps): screened min+argmin; flags for own codes ----
        float d0c = s_cn[lane]      - 2.f * s_s[lane];
        float d1c = s_cn[lane + 32] - 2.f * s_s[lane + 32];
        float dm = d0c; int im = lane;
        if (d1c < dm) { dm = d1c; im = lane + 32; }
#pragma unroll
        for (int off = 16; off; off >>= 1) {
            float od = __shfl_xor_sync(0xffffffffu, dm, off);
            int   oi = __shfl_xor_sync(0xffffffffu, im, off);
            if (od < dm || (od == dm && oi < im)) { dm = od; im = oi; }
        }
        // im/dm now uniform across block (identical computation per warp)
        const int jb = 2 * w;
        float srcv = (jb < 32) ? d0c : d1c;
        float dj0 = __shfl_sync(0xffffffffu, srcv, jb & 31);
        float dj1 = __shfl_sync(0xffffffffu, srcv, (jb & 31) + 1);

        // speculative prefetch of next state row (screen argmin) — issue first
        {
            const float* gh = g_Ghh + (size_t)im * G3D;
            pf_gh0 = gh[tid]; pf_gh1 = gh[1024 + tid]; pf_gh2 = gh[2048 + tid];
            pf_cur = g_cb[(size_t)im * DDIM + tid];
            spec_k = im;
        }

        // ---- phase D: exact fp32 recheck of flagged own codes ----
        {
            const float4* z4 = (const float4*)zbuf;
            const float thr = dm + SCREEN_MARGIN;
#pragma unroll
            for (int jj = 0; jj < 2; jj++) {
                const int j = jb + jj;
                const float dj = jj ? dj1 : dj0;
                float dx = INFINITY;
                if (dj <= thr) {
                    const float4* cr = (const float4*)(g_cb + (size_t)j * DDIM);
                    float acc = 0.f;
#pragma unroll
                    for (int q = 0; q < 8; q++) {
                        float4 c = cr[lane + 32 * q];
                        float4 z = z4[lane + 32 * q];
                        float e0 = z.x - c.x, e1 = z.y - c.y;
                        float e2 = z.z - c.z, e3 = z.w - c.w;
                        acc += e0 * e0 + e1 * e1 + e2 * e2 + e3 * e3;
                    }
#pragma unroll
                    for (int off = 16; off; off >>= 1)
                        acc += __shfl_down_sync(0xffffffffu, acc, off);
                    dx = acc;
                }
                if (lane == 0) s_d[j] = dx;
            }
        }
        __syncthreads();                       // sync 3

        // ---- phase E: warp 0 exact argmin, state update, record ----
        if (w == 0) {
            float e0 = s_d[lane];
            float e1 = s_d[lane + 32];
            int i0 = lane;
            if (e1 < e0) { e0 = e1; i0 = lane + 32; }
#pragma unroll
            for (int off = 16; off; off >>= 1) {
                float en = __shfl_down_sync(0xffffffffu, e0, off);
                int   in_ = __shfl_down_sync(0xffffffffu, i0, off);
                if (en < e0 || (en == e0 && in_ < i0)) { e0 = en; i0 = in_; }
            }
            if (lane == 0) {
                s_idx = i0;
                s_code[sw] = i0;
                s_outk[i] = (unsigned char)i0;
                commit_acc += e0 * (1.f / 1024.f);
            }
        }
        __syncthreads();                       // sync 4
        // spec stays valid iff final choice == screen argmin
        if (s_idx != im) spec_k = -1;
    }

    if (tid == 0) { g_commit[b] = commit_acc; g_nupd[b] = n_act; }
    __syncthreads();

    // ---- deferred injection flush (last-writer-wins per seq position) ----
    for (int i = w; i < n_act; i += 32) {
        const int p = s_p2[i];
        bool dup = false;
        for (int j = i + 1 + lane; j < n_act; j += 32)
            dup |= (s_p2[j] == p);
        dup = __any_sync(0xffffffffu, dup);
        if (!dup) {
            const int k = s_outk[i];
            const float4* src = (const float4*)(g_injT + (size_t)k * DDIM);
            float4* dst = (float4*)(out + ((size_t)b * TDIM + p) * DDIM);
#pragma unroll
            for (int e = 0; e < 8; e++)
                dst[lane + 32 * e] = src[lane + 32 * e];
        }
    }
}

__global__ void finalize_k(float* out, long long sidx, long long out_size) {
    if (threadIdx.x == 0 && blockIdx.x == 0) {
        float tc = 0.f;
        int nu = 0;
        for (int i = 0; i < BDIM; i++) { tc += g_commit[i]; nu += g_nupd[i]; }
        if (sidx < out_size)
            out[sidx] = tc / (float)(nu > 0 ? nu : 1);
    }
}

extern "C" void kernel_launch(void* const* d_in, const int* in_sizes, int n_in,
                              void* d_out, int out_size) {
    const float* h    = (const float*)d_in[0];
    const int*   bidx = (const int*)d_in[1];
    const int*   spos = (const int*)d_in[2];
    const int*   tok  = (const int*)d_in[3];
    const int*   ctag = nullptr;
    int o = 4;
    if (n_in >= 11) { ctag = (const int*)d_in[4]; o = 5; }
    const float* W_ih  = (const float*)d_in[o + 0];
    const float* W_hh  = (const float*)d_in[o + 1];
    const float* b_ih  = (const float*)d_in[o + 2];
    const float* b_hh  = (const float*)d_in[o + 3];
    const float* cb    = (const float*)d_in[o + 4];
    const float* W_inj = (const float*)d_in[o + 5];
    float* out = (float*)d_out;

    static int smem_set = 0;
    if (!smem_set) {
        cudaFuncSetAttribute(serial_scan,
                             cudaFuncAttributeMaxDynamicSharedMemorySize,
                             KCB * (DDIM / 2) * (int)sizeof(__nv_bfloat162));
        smem_set = 1;
    }

    cudaMemsetAsync(out, 0, (size_t)out_size * sizeof(float), 0);
    gather_x<<<NTAGS, 256>>>(h, bidx, spos);
    prep_cb<<<KCB + 1, 256>>>(cb);
    fused_gemm<<<496, 128>>>(h, bidx, spos, W_ih, b_ih, W_hh, b_hh, W_inj);
    serial_scan<<<BDIM, 1024, KCB * (DDIM / 2) * (int)sizeof(__nv_bfloat162)>>>(
        bidx, spos, tok, ctag, out);
    finalize_k<<<1, 32>>>(out, (long long)BDIM * TDIM * DDIM, (long long)out_size);
}